// round 2
// baseline (speedup 1.0000x reference)
#include <cuda_runtime.h>
#include <cstdint>

// Problem shape (fixed by the dataset): q,k,v [4, 16, 2048, 64] fp32.
#define BATCH 4
#define HEADS 16
#define SEQ   2048
#define HDIM  64

#define QT 128           // q rows per CTA
#define KT 64            // keys per smem tile
#define NWARP 8          // 256 threads; each warp owns 16 q rows
#define KSTRIDE 68       // smem row stride (floats) for K tile  -> conflict-free B-frag loads
#define VSTRIDE 72       // smem row stride (floats) for V tile  -> conflict-free B-frag loads

static __device__ __forceinline__ float fast_ex2(float x) {
    float r;
    asm("ex2.approx.f32 %0, %1;" : "=f"(r) : "f"(x));
    return r;
}

// round-to-nearest fp32 -> tf32 (kept as f32 bit pattern)
static __device__ __forceinline__ float to_tf32(float x) {
    uint32_t u;
    asm("cvt.rna.tf32.f32 %0, %1;" : "=r"(u) : "f"(x));
    return __uint_as_float(u);
}

// D(16x8,f32) += A(16x8,tf32) * B(8x8,tf32), row.col
static __device__ __forceinline__ void mma_tf32(float d[4], const float a[4],
                                                float b0, float b1) {
    asm("mma.sync.aligned.m16n8k8.row.col.f32.tf32.tf32.f32 "
        "{%0,%1,%2,%3}, {%4,%5,%6,%7}, {%8,%9}, {%0,%1,%2,%3};\n"
        : "+f"(d[0]), "+f"(d[1]), "+f"(d[2]), "+f"(d[3])
        : "r"(__float_as_uint(a[0])), "r"(__float_as_uint(a[1])),
          "r"(__float_as_uint(a[2])), "r"(__float_as_uint(a[3])),
          "r"(__float_as_uint(b0)),  "r"(__float_as_uint(b1)));
}

__global__ void __launch_bounds__(NWARP * 32, 2)
attn_tf32_kernel(const float* __restrict__ q,
                 const float* __restrict__ k,
                 const float* __restrict__ v,
                 float* __restrict__ out)
{
    __shared__ float Ks[KT][KSTRIDE];
    __shared__ float Vs[KT][VSTRIDE];

    const int bh    = blockIdx.y;            // 0..63
    const int qtile = blockIdx.x;            // 0..15
    const int tid   = threadIdx.x;
    const int wid   = tid >> 5;
    const int lane  = tid & 31;
    const int g     = lane >> 2;             // groupID (row within m16)
    const int t     = lane & 3;              // threadID in group

    const size_t base = (size_t)bh * SEQ * HDIM;
    const float* Qp = q + base + (size_t)qtile * QT * HDIM;
    const float* Kp = k + base;
    const float* Vp = v + base;
    float*       Op = out + base + (size_t)qtile * QT * HDIM;

    // ---- Load Q fragments (held in registers for the whole kernel) ----
    // Prescale by softmax scale (1/8) * log2(e) so softmax uses ex2 directly.
    const float qscale = 0.125f * 1.4426950408889634f;
    float a[8][4];
    {
        const int r0 = wid * 16 + g;
        #pragma unroll
        for (int kc = 0; kc < 8; kc++) {
            a[kc][0] = to_tf32(Qp[(size_t)(r0    ) * HDIM + kc * 8 + t    ] * qscale);
            a[kc][1] = to_tf32(Qp[(size_t)(r0 + 8) * HDIM + kc * 8 + t    ] * qscale);
            a[kc][2] = to_tf32(Qp[(size_t)(r0    ) * HDIM + kc * 8 + t + 4] * qscale);
            a[kc][3] = to_tf32(Qp[(size_t)(r0 + 8) * HDIM + kc * 8 + t + 4] * qscale);
        }
    }

    float o[8][4];
    #pragma unroll
    for (int n = 0; n < 8; n++) { o[n][0] = o[n][1] = o[n][2] = o[n][3] = 0.f; }

    float m0 = -1e30f;   // safe "-inf" sentinel (avoids inf-inf NaN paths)
    float m1 = -1e30f;
    float l0 = 0.f, l1 = 0.f;

    for (int kt = 0; kt < SEQ; kt += KT) {
        __syncthreads();
        // ---- Stage K,V tile into smem (tf32-rounded) ----
        #pragma unroll
        for (int i = 0; i < 4; i++) {
            int idx = tid + i * 256;          // 0..1023 covers 64x64/4
            int row = idx >> 4;
            int c   = (idx & 15) << 2;
            float4 kv = *(const float4*)(Kp + (size_t)(kt + row) * HDIM + c);
            Ks[row][c + 0] = to_tf32(kv.x);
            Ks[row][c + 1] = to_tf32(kv.y);
            Ks[row][c + 2] = to_tf32(kv.z);
            Ks[row][c + 3] = to_tf32(kv.w);
            float4 vv = *(const float4*)(Vp + (size_t)(kt + row) * HDIM + c);
            Vs[row][c + 0] = to_tf32(vv.x);
            Vs[row][c + 1] = to_tf32(vv.y);
            Vs[row][c + 2] = to_tf32(vv.z);
            Vs[row][c + 3] = to_tf32(vv.w);
        }
        __syncthreads();

        // ---- S = (Q*scale) @ K^T   [16 x 64 per warp] ----
        float s[8][4];
        #pragma unroll
        for (int n = 0; n < 8; n++) { s[n][0] = s[n][1] = s[n][2] = s[n][3] = 0.f; }

        #pragma unroll
        for (int kc = 0; kc < 8; kc++) {
            #pragma unroll
            for (int n = 0; n < 8; n++) {
                // B[k=d, n=key] = K[key][d]; b0:(t, g), b1:(t+4, g)
                float b0 = Ks[n * 8 + g][kc * 8 + t];
                float b1 = Ks[n * 8 + g][kc * 8 + t + 4];
                mma_tf32(s[n], a[kc], b0, b1);
            }
        }

        // ---- Online softmax (rows g and g+8 per thread) ----
        float mx0 = -1e30f, mx1 = -1e30f;
        #pragma unroll
        for (int n = 0; n < 8; n++) {
            mx0 = fmaxf(mx0, fmaxf(s[n][0], s[n][1]));
            mx1 = fmaxf(mx1, fmaxf(s[n][2], s[n][3]));
        }
        mx0 = fmaxf(mx0, __shfl_xor_sync(0xffffffffu, mx0, 1));
        mx0 = fmaxf(mx0, __shfl_xor_sync(0xffffffffu, mx0, 2));
        mx1 = fmaxf(mx1, __shfl_xor_sync(0xffffffffu, mx1, 1));
        mx1 = fmaxf(mx1, __shfl_xor_sync(0xffffffffu, mx1, 2));

        float nm0 = fmaxf(m0, mx0);
        float nm1 = fmaxf(m1, mx1);
        float al0 = fast_ex2(m0 - nm0);
        float al1 = fast_ex2(m1 - nm1);
        m0 = nm0; m1 = nm1;

        float rs0 = 0.f, rs1 = 0.f;
        #pragma unroll
        for (int n = 0; n < 8; n++) {
            s[n][0] = fast_ex2(s[n][0] - m0);
            s[n][1] = fast_ex2(s[n][1] - m0);
            s[n][2] = fast_ex2(s[n][2] - m1);
            s[n][3] = fast_ex2(s[n][3] - m1);
            rs0 += s[n][0] + s[n][1];
            rs1 += s[n][2] + s[n][3];
        }
        rs0 += __shfl_xor_sync(0xffffffffu, rs0, 1);
        rs0 += __shfl_xor_sync(0xffffffffu, rs0, 2);
        rs1 += __shfl_xor_sync(0xffffffffu, rs1, 1);
        rs1 += __shfl_xor_sync(0xffffffffu, rs1, 2);
        l0 = l0 * al0 + rs0;
        l1 = l1 * al1 + rs1;

        #pragma unroll
        for (int n = 0; n < 8; n++) {
            o[n][0] *= al0; o[n][1] *= al0;
            o[n][2] *= al1; o[n][3] *= al1;
        }

        // ---- O += P @ V ----
        #pragma unroll
        for (int kk = 0; kk < 8; kk++) {
            // Rearrange P chunk kk from C-fragment layout to A-fragment layout.
            // Target a0 = P[g][8kk + t], a2 = P[g][8kk + t + 4]; a1/a3 rows +8.
            // Col x lives in lane (base | x>>1), reg (x&1 ? c1 : c0).
            int srcA = (lane & ~3) | (t >> 1);
            int srcB = srcA + 2;
            float e0A = __shfl_sync(0xffffffffu, s[kk][0], srcA);
            float e1A = __shfl_sync(0xffffffffu, s[kk][1], srcA);
            float e0B = __shfl_sync(0xffffffffu, s[kk][0], srcB);
            float e1B = __shfl_sync(0xffffffffu, s[kk][1], srcB);
            float e2A = __shfl_sync(0xffffffffu, s[kk][2], srcA);
            float e3A = __shfl_sync(0xffffffffu, s[kk][3], srcA);
            float e2B = __shfl_sync(0xffffffffu, s[kk][2], srcB);
            float e3B = __shfl_sync(0xffffffffu, s[kk][3], srcB);
            float pa[4];
            pa[0] = (t & 1) ? e1A : e0A;
            pa[1] = (t & 1) ? e3A : e2A;
            pa[2] = (t & 1) ? e1B : e0B;
            pa[3] = (t & 1) ? e3B : e2B;

            #pragma unroll
            for (int n = 0; n < 8; n++) {
                // B[k=key, n=d] = V[key][d]; b0:(t, g), b1:(t+4, g)
                float b0 = Vs[kk * 8 + t    ][n * 8 + g];
                float b1 = Vs[kk * 8 + t + 4][n * 8 + g];
                mma_tf32(o[n], pa, b0, b1);
            }
        }
    }

    // ---- Epilogue: normalize and store ----
    const float il0 = 1.0f / l0;
    const float il1 = 1.0f / l1;
    const int r0 = wid * 16 + g;
    #pragma unroll
    for (int n = 0; n < 8; n++) {
        float2 w0 = make_float2(o[n][0] * il0, o[n][1] * il0);
        float2 w1 = make_float2(o[n][2] * il1, o[n][3] * il1);
        *(float2*)(Op + (size_t)(r0    ) * HDIM + n * 8 + 2 * t) = w0;
        *(float2*)(Op + (size_t)(r0 + 8) * HDIM + n * 8 + 2 * t) = w1;
    }
}

extern "C" void kernel_launch(void* const* d_in, const int* in_sizes, int n_in,
                              void* d_out, int out_size)
{
    (void)in_sizes; (void)n_in; (void)out_size;
    const float* q = (const float*)d_in[0];
    const float* k = (const float*)d_in[1];
    const float* v = (const float*)d_in[2];
    float* out = (float*)d_out;

    dim3 grid(SEQ / QT, BATCH * HEADS);   // (16, 64)
    dim3 block(NWARP * 32);               // 256
    attn_tf32_kernel<<<grid, block>>>(q, k, v, out);
}

// round 4
// speedup vs baseline: 1.7340x; 1.7340x over previous
#include <cuda_runtime.h>
#include <cuda_fp16.h>
#include <cstdint>

// Problem shape (fixed by the dataset): q,k,v [4, 16, 2048, 64] fp32.
#define BATCH 4
#define HEADS 16
#define SEQ   2048
#define HDIM  64

#define QT 128           // q rows per CTA
#define KT 64            // keys per smem tile
#define NWARP 8          // 256 threads; each warp owns 16 q rows

// Smem layouts (element = uint32 = half2):
//  Ks[key][pair d/2]   : stride 36 u32  (36 mod 32 == 4 -> banks 4g+t, conflict-free B loads)
//  Vp[keypair][d]      : stride 72 u32  (72 mod 32 == 8 -> banks 8t+g, conflict-free B loads)
#define KS_STRIDE 36
#define VP_STRIDE 72

static __device__ __forceinline__ float fast_ex2(float x) {
    float r;
    asm("ex2.approx.f32 %0, %1;" : "=f"(r) : "f"(x));
    return r;
}

static __device__ __forceinline__ uint32_t f2h2(float lo, float hi) {
    __half2 h = __floats2half2_rn(lo, hi);
    return *(uint32_t*)&h;
}

// D(16x8,f32) += A(16x16,f16) * B(16x8,f16), row.col
static __device__ __forceinline__ void mma_f16(float d[4],
                                               uint32_t a0, uint32_t a1,
                                               uint32_t a2, uint32_t a3,
                                               uint32_t b0, uint32_t b1) {
    asm("mma.sync.aligned.m16n8k16.row.col.f32.f16.f16.f32 "
        "{%0,%1,%2,%3}, {%4,%5,%6,%7}, {%8,%9}, {%0,%1,%2,%3};\n"
        : "+f"(d[0]), "+f"(d[1]), "+f"(d[2]), "+f"(d[3])
        : "r"(a0), "r"(a1), "r"(a2), "r"(a3), "r"(b0), "r"(b1));
}

__global__ void __launch_bounds__(NWARP * 32, 2)
attn_f16_kernel(const float* __restrict__ q,
                const float* __restrict__ k,
                const float* __restrict__ v,
                float* __restrict__ out)
{
    __shared__ uint32_t Ks[KT][KS_STRIDE];        // half2: K[key][2d, 2d+1]
    __shared__ uint32_t Vp[KT / 2][VP_STRIDE];    // half2: {V[2p][d], V[2p+1][d]}

    const int bh    = blockIdx.y;            // 0..63
    const int qtile = blockIdx.x;            // 0..15
    const int tid   = threadIdx.x;
    const int wid   = tid >> 5;
    const int lane  = tid & 31;
    const int g     = lane >> 2;             // groupID (row within m16)
    const int t     = lane & 3;              // threadID in group

    const size_t base = (size_t)bh * SEQ * HDIM;
    const float* Qp = q + base + (size_t)qtile * QT * HDIM;
    const float* Kp = k + base;
    const float* Vp_g = v + base;
    float*       Op = out + base + (size_t)qtile * QT * HDIM;

    // ---- Load Q fragments as fp16 (held in registers for the whole kernel) ----
    // Prescale by softmax scale (1/8) * log2(e) so softmax uses ex2 directly.
    const float qscale = 0.125f * 1.4426950408889634f;
    uint32_t a[4][4];   // [kc][frag]; kc covers k=16kc..16kc+15
    {
        const int r0 = wid * 16 + g;
        #pragma unroll
        for (int kc = 0; kc < 4; kc++) {
            const float* q0 = Qp + (size_t)r0 * HDIM + kc * 16;
            const float* q1 = Qp + (size_t)(r0 + 8) * HDIM + kc * 16;
            a[kc][0] = f2h2(q0[2*t    ] * qscale, q0[2*t + 1] * qscale);
            a[kc][1] = f2h2(q1[2*t    ] * qscale, q1[2*t + 1] * qscale);
            a[kc][2] = f2h2(q0[2*t + 8] * qscale, q0[2*t + 9] * qscale);
            a[kc][3] = f2h2(q1[2*t + 8] * qscale, q1[2*t + 9] * qscale);
        }
    }

    float o[8][4];
    #pragma unroll
    for (int n = 0; n < 8; n++) { o[n][0] = o[n][1] = o[n][2] = o[n][3] = 0.f; }

    float m0 = -1e30f, m1 = -1e30f;   // safe "-inf" sentinel
    float l0 = 0.f, l1 = 0.f;

    for (int kt = 0; kt < SEQ; kt += KT) {
        __syncthreads();
        // ---- Stage K tile: fp16 [key][d] pairs; 64x64 / (4 per thread) = 4 iters ----
        #pragma unroll
        for (int i = 0; i < 4; i++) {
            int idx = tid + i * 256;          // 0..1023
            int row = idx >> 4;               // key 0..63
            int c   = (idx & 15) << 2;        // d 0..60 step 4
            float4 kv = *(const float4*)(Kp + (size_t)(kt + row) * HDIM + c);
            uint2 hp;
            hp.x = f2h2(kv.x, kv.y);
            hp.y = f2h2(kv.z, kv.w);
            *(uint2*)&Ks[row][c >> 1] = hp;   // 8B aligned: (row*36 + c/2)*4, c/2 even
        }
        // ---- Stage V tile pre-paired: Vp[p][d] = {V[2p][d], V[2p+1][d]} ----
        #pragma unroll
        for (int i = 0; i < 2; i++) {
            int idx = tid + i * 256;          // 0..511
            int p   = idx >> 4;               // key pair 0..31
            int c   = (idx & 15) << 2;        // d 0..60 step 4
            float4 v0 = *(const float4*)(Vp_g + (size_t)(kt + 2*p    ) * HDIM + c);
            float4 v1 = *(const float4*)(Vp_g + (size_t)(kt + 2*p + 1) * HDIM + c);
            uint4 hp;
            hp.x = f2h2(v0.x, v1.x);
            hp.y = f2h2(v0.y, v1.y);
            hp.z = f2h2(v0.z, v1.z);
            hp.w = f2h2(v0.w, v1.w);
            *(uint4*)&Vp[p][c] = hp;          // 16B aligned: (p*72 + c)*4
        }
        __syncthreads();

        // ---- S = (Q*scale) @ K^T   [16 x 64 per warp] ----
        float s[8][4];
        #pragma unroll
        for (int n = 0; n < 8; n++) { s[n][0] = s[n][1] = s[n][2] = s[n][3] = 0.f; }

        #pragma unroll
        for (int kc = 0; kc < 4; kc++) {
            #pragma unroll
            for (int n = 0; n < 8; n++) {
                // B[k=d][n=key] = K[key][d]; b0: d-pairs 8kc+t, b1: 8kc+t+4, key row n*8+g
                uint32_t b0 = Ks[n * 8 + g][8 * kc + t];
                uint32_t b1 = Ks[n * 8 + g][8 * kc + t + 4];
                mma_f16(s[n], a[kc][0], a[kc][1], a[kc][2], a[kc][3], b0, b1);
            }
        }

        // ---- Online softmax (rows g and g+8 per thread) ----
        float mx0 = -1e30f, mx1 = -1e30f;
        #pragma unroll
        for (int n = 0; n < 8; n++) {
            mx0 = fmaxf(mx0, fmaxf(s[n][0], s[n][1]));
            mx1 = fmaxf(mx1, fmaxf(s[n][2], s[n][3]));
        }
        mx0 = fmaxf(mx0, __shfl_xor_sync(0xffffffffu, mx0, 1));
        mx0 = fmaxf(mx0, __shfl_xor_sync(0xffffffffu, mx0, 2));
        mx1 = fmaxf(mx1, __shfl_xor_sync(0xffffffffu, mx1, 1));
        mx1 = fmaxf(mx1, __shfl_xor_sync(0xffffffffu, mx1, 2));

        float nm0 = fmaxf(m0, mx0);
        float nm1 = fmaxf(m1, mx1);
        float al0 = fast_ex2(m0 - nm0);
        float al1 = fast_ex2(m1 - nm1);
        m0 = nm0; m1 = nm1;

        float rs0 = 0.f, rs1 = 0.f;
        #pragma unroll
        for (int n = 0; n < 8; n++) {
            s[n][0] = fast_ex2(s[n][0] - m0);
            s[n][1] = fast_ex2(s[n][1] - m0);
            s[n][2] = fast_ex2(s[n][2] - m1);
            s[n][3] = fast_ex2(s[n][3] - m1);
            rs0 += s[n][0] + s[n][1];
            rs1 += s[n][2] + s[n][3];
        }
        rs0 += __shfl_xor_sync(0xffffffffu, rs0, 1);
        rs0 += __shfl_xor_sync(0xffffffffu, rs0, 2);
        rs1 += __shfl_xor_sync(0xffffffffu, rs1, 1);
        rs1 += __shfl_xor_sync(0xffffffffu, rs1, 2);
        l0 = l0 * al0 + rs0;
        l1 = l1 * al1 + rs1;

        #pragma unroll
        for (int n = 0; n < 8; n++) {
            o[n][0] *= al0; o[n][1] *= al0;
            o[n][2] *= al1; o[n][3] *= al1;
        }

        // ---- O += P @ V ----
        // m16n8k16 C-fragment maps directly onto the A-fragment: no shuffles.
        #pragma unroll
        for (int kc = 0; kc < 4; kc++) {     // keys 16kc .. 16kc+15
            uint32_t pa0 = f2h2(s[2*kc    ][0], s[2*kc    ][1]);  // row g,   keys 16kc+2t,+1
            uint32_t pa1 = f2h2(s[2*kc    ][2], s[2*kc    ][3]);  // row g+8
            uint32_t pa2 = f2h2(s[2*kc + 1][0], s[2*kc + 1][1]);  // row g,   keys 16kc+8+2t,+1
            uint32_t pa3 = f2h2(s[2*kc + 1][2], s[2*kc + 1][3]);  // row g+8

            #pragma unroll
            for (int nn = 0; nn < 8; nn++) {
                // B[k=key][n=d] = V; b0: key-pairs 8kc+t, b1: 8kc+t+4, d col nn*8+g
                uint32_t b0 = Vp[8 * kc + t    ][nn * 8 + g];
                uint32_t b1 = Vp[8 * kc + t + 4][nn * 8 + g];
                mma_f16(o[nn], pa0, pa1, pa2, pa3, b0, b1);
            }
        }
    }

    // ---- Epilogue: normalize and store ----
    const float il0 = 1.0f / l0;
    const float il1 = 1.0f / l1;
    const int r0 = wid * 16 + g;
    #pragma unroll
    for (int n = 0; n < 8; n++) {
        float2 w0 = make_float2(o[n][0] * il0, o[n][1] * il0);
        float2 w1 = make_float2(o[n][2] * il1, o[n][3] * il1);
        *(float2*)(Op + (size_t)(r0    ) * HDIM + n * 8 + 2 * t) = w0;
        *(float2*)(Op + (size_t)(r0 + 8) * HDIM + n * 8 + 2 * t) = w1;
    }
}

extern "C" void kernel_launch(void* const* d_in, const int* in_sizes, int n_in,
                              void* d_out, int out_size)
{
    (void)in_sizes; (void)n_in; (void)out_size;
    const float* q = (const float*)d_in[0];
    const float* k = (const float*)d_in[1];
    const float* v = (const float*)d_in[2];
    float* out = (float*)d_out;

    dim3 grid(SEQ / QT, BATCH * HEADS);   // (16, 64)
    dim3 block(NWARP * 32);               // 256
    attn_f16_kernel<<<grid, block>>>(q, k, v, out);
}